// round 1
// baseline (speedup 1.0000x reference)
#include <cuda_runtime.h>
#include <math.h>

#define BATCH   2
#define LSEQ    2048
#define DM      1024
#define DI      2048
#define DSTATE  64
#define HD      64
#define NH      32
#define CONVDIM 2176
#define DINPROJ 4256
#define ROWS    (BATCH*LSEQ)
#define EPSF    1e-5f

// ---------------- scratch (static device globals: no allocations allowed) ----------------
__device__ float g_ln1[(size_t)ROWS*DM];
__device__ float g_zx [(size_t)ROWS*DINPROJ];
__device__ float g_xbc[(size_t)ROWS*CONVDIM];
__device__ float g_dt [(size_t)ROWS*NH];
__device__ float g_y  [(size_t)ROWS*DI];
__device__ float g_x1 [(size_t)ROWS*DM];
__device__ float g_ln2[(size_t)ROWS*DM];
__device__ float g_mlp[(size_t)ROWS*4*DM];

// ---------------- layernorm ----------------
__global__ void ln_kernel(const float* __restrict__ in, const float* __restrict__ w,
                          const float* __restrict__ b, float* __restrict__ out)
{
    int row = blockIdx.x;
    const float* x = in + (size_t)row*DM;
    float s = 0.f, ss = 0.f;
    for (int c = threadIdx.x; c < DM; c += 256) {
        float v = x[c];
        s += v; ss += v*v;
    }
    __shared__ float red0[8], red1[8];
    #pragma unroll
    for (int o = 16; o; o >>= 1) {
        s  += __shfl_xor_sync(0xffffffffu, s, o);
        ss += __shfl_xor_sync(0xffffffffu, ss, o);
    }
    int warp = threadIdx.x >> 5, lane = threadIdx.x & 31;
    if (lane == 0) { red0[warp] = s; red1[warp] = ss; }
    __syncthreads();
    s = 0.f; ss = 0.f;
    #pragma unroll
    for (int i = 0; i < 8; i++) { s += red0[i]; ss += red1[i]; }
    float mu  = s * (1.f/DM);
    float var = ss * (1.f/DM) - mu*mu;
    float sc  = rsqrtf(var + EPSF);
    float* o = out + (size_t)row*DM;
    for (int c = threadIdx.x; c < DM; c += 256)
        o[c] = (x[c] - mu) * sc * w[c] + b[c];
}

// ---------------- GEMM: C[M,N] = A[M,K] @ B[N,K]^T  (+epilogue) ----------------
// EPI: 0=none, 1=+add, 2=+bias then gelu(exact), 3=+bias+add
template<int EPI>
__global__ void __launch_bounds__(256)
gemm_nt(const float* __restrict__ A, const float* __restrict__ B,
        float* __restrict__ C, int M, int N, int K,
        const float* __restrict__ add, const float* __restrict__ bias)
{
    __shared__ float As[8][128];
    __shared__ float Bs[8][128];
    int tid = threadIdx.x;
    int bm = blockIdx.y * 128, bn = blockIdx.x * 128;
    int tx = tid & 15, ty = tid >> 4;
    int lr = tid >> 1, lk = (tid & 1) * 4;
    const float* Ap = A + (size_t)(bm + lr)*K + lk;
    const float* Bp = B + (size_t)(bn + lr)*K + lk;
    bool bval = (bn + lr) < N;

    float acc[8][8];
    #pragma unroll
    for (int i = 0; i < 8; i++)
        #pragma unroll
        for (int j = 0; j < 8; j++) acc[i][j] = 0.f;

    float4 av = *(const float4*)Ap;
    float4 bv = bval ? *(const float4*)Bp : make_float4(0.f,0.f,0.f,0.f);

    for (int k0 = 0; k0 < K; k0 += 8) {
        As[lk+0][lr] = av.x; As[lk+1][lr] = av.y; As[lk+2][lr] = av.z; As[lk+3][lr] = av.w;
        Bs[lk+0][lr] = bv.x; Bs[lk+1][lr] = bv.y; Bs[lk+2][lr] = bv.z; Bs[lk+3][lr] = bv.w;
        __syncthreads();
        if (k0 + 8 < K) {
            av = *(const float4*)(Ap + k0 + 8);
            bv = bval ? *(const float4*)(Bp + k0 + 8) : make_float4(0.f,0.f,0.f,0.f);
        }
        #pragma unroll
        for (int k = 0; k < 8; k++) {
            float a[8], bb[8];
            #pragma unroll
            for (int i = 0; i < 8; i++) a[i]  = As[k][ty*8 + i];
            #pragma unroll
            for (int j = 0; j < 8; j++) bb[j] = Bs[k][tx*8 + j];
            #pragma unroll
            for (int i = 0; i < 8; i++)
                #pragma unroll
                for (int j = 0; j < 8; j++)
                    acc[i][j] = fmaf(a[i], bb[j], acc[i][j]);
        }
        __syncthreads();
    }

    #pragma unroll
    for (int i = 0; i < 8; i++) {
        int row = bm + ty*8 + i;
        #pragma unroll
        for (int j = 0; j < 8; j++) {
            int col = bn + tx*8 + j;
            if (col < N) {
                float v = acc[i][j];
                size_t idx = (size_t)row*N + col;
                if (EPI == 1) v += add[idx];
                if (EPI == 2) { v += bias[col]; v = 0.5f*v*(1.f + erff(v*0.70710678118f)); }
                if (EPI == 3) { v += bias[col] + add[idx]; }
                C[idx] = v;
            }
        }
    }
}

// ---------------- conv1d(width4, causal) + SiLU + dt softplus ----------------
__global__ void conv_kernel(const float* __restrict__ conv_w, const float* __restrict__ conv_b,
                            const float* __restrict__ dt_bias)
{
    int r = blockIdx.x;
    int b = r >> 11, l = r & (LSEQ-1);
    for (int c = threadIdx.x; c < CONVDIM; c += 256) {
        float acc = conv_b[c];
        #pragma unroll
        for (int k = 0; k < 4; k++) {
            int ll = l + k - 3;
            if (ll >= 0)
                acc = fmaf(g_zx[(size_t)(b*LSEQ + ll)*DINPROJ + DI + c], conv_w[c*4 + k], acc);
        }
        acc = acc / (1.f + expf(-acc));   // SiLU
        g_xbc[(size_t)r*CONVDIM + c] = acc;
    }
    if (threadIdx.x < NH) {
        int hh = threadIdx.x;
        float raw = g_zx[(size_t)r*DINPROJ + DI + CONVDIM + hh] + dt_bias[hh];
        g_dt[r*NH + hh] = (raw > 20.f) ? raw : log1pf(expf(raw));
    }
}

// ---------------- selective scan: one block per (batch, head) ----------------
__global__ void __launch_bounds__(256) scan_kernel(const float* __restrict__ A_log,
                                                   const float* __restrict__ Dvec)
{
    int bh = blockIdx.x;
    int b = bh >> 5, h = bh & 31;
    int t = threadIdx.x;
    int p = t >> 2, nq = t & 3;   // p: headdim row, nq: quarter of state dim

    float A_h = -expf(A_log[h]);
    float Dh  = Dvec[h];

    __shared__ float sX[2][64], sB[2][64], sC[2][64];
    __shared__ float sdt[2];

    const size_t base0 = (size_t)(b*LSEQ)*CONVDIM;
    auto load = [&](int buf, int l) {
        size_t rb = base0 + (size_t)l*CONVDIM;
        if (t < 64)        sX[buf][t]       = g_xbc[rb + h*HD + t];
        else if (t < 128)  sB[buf][t-64]    = g_xbc[rb + DI + (t-64)];
        else if (t < 192)  sC[buf][t-128]   = g_xbc[rb + DI + DSTATE + (t-128)];
        else if (t == 192) sdt[buf]         = g_dt[(b*LSEQ + l)*NH + h];
    };

    load(0, 0);
    __syncthreads();

    float st[16];
    #pragma unroll
    for (int i = 0; i < 16; i++) st[i] = 0.f;

    for (int l = 0; l < LSEQ; l++) {
        int buf = l & 1;
        if (l + 1 < LSEQ) load(buf ^ 1, l + 1);

        float dtv  = sdt[buf];
        float dA   = expf(dtv * A_h);
        float xv   = sX[buf][p];
        float coef = dtv * xv;

        const float* Bp = &sB[buf][nq*16];
        const float* Cp = &sC[buf][nq*16];
        float acc = 0.f;
        #pragma unroll
        for (int i = 0; i < 16; i++) {
            float s2 = fmaf(st[i], dA, coef * Bp[i]);
            st[i] = s2;
            acc = fmaf(s2, Cp[i], acc);
        }
        acc += __shfl_xor_sync(0xffffffffu, acc, 1);
        acc += __shfl_xor_sync(0xffffffffu, acc, 2);
        if (nq == 0)
            g_y[(size_t)(b*LSEQ + l)*DI + h*HD + p] = acc + xv * Dh;
        __syncthreads();
    }
}

// ---------------- gate (y * silu(z)) + RMSNorm ----------------
__global__ void gate_rms_kernel(const float* __restrict__ norm_w)
{
    int r = blockIdx.x;
    size_t zb = (size_t)r*DINPROJ;
    size_t yb = (size_t)r*DI;
    float ss = 0.f;
    for (int c = threadIdx.x; c < DI; c += 256) {
        float z = g_zx[zb + c];
        float v = g_y[yb + c] * (z / (1.f + expf(-z)));
        g_y[yb + c] = v;
        ss += v*v;
    }
    __shared__ float red[8];
    #pragma unroll
    for (int o = 16; o; o >>= 1) ss += __shfl_xor_sync(0xffffffffu, ss, o);
    if ((threadIdx.x & 31) == 0) red[threadIdx.x >> 5] = ss;
    __syncthreads();
    ss = 0.f;
    #pragma unroll
    for (int i = 0; i < 8; i++) ss += red[i];
    float sc = rsqrtf(ss * (1.f/DI) + EPSF);
    for (int c = threadIdx.x; c < DI; c += 256)
        g_y[yb + c] = g_y[yb + c] * sc * norm_w[c];
}

// ---------------- launch ----------------
extern "C" void kernel_launch(void* const* d_in, const int* in_sizes, int n_in,
                              void* d_out, int out_size)
{
    const float* x          = (const float*)d_in[0];
    const float* ln1_w      = (const float*)d_in[1];
    const float* ln1_b      = (const float*)d_in[2];
    const float* in_proj_w  = (const float*)d_in[3];
    const float* conv_w     = (const float*)d_in[4];
    const float* conv_b     = (const float*)d_in[5];
    const float* dt_bias    = (const float*)d_in[6];
    const float* A_log      = (const float*)d_in[7];
    const float* Dvec       = (const float*)d_in[8];
    const float* norm_w     = (const float*)d_in[9];
    const float* out_proj_w = (const float*)d_in[10];
    const float* ln2_w      = (const float*)d_in[11];
    const float* ln2_b      = (const float*)d_in[12];
    const float* mlp_w1     = (const float*)d_in[13];
    const float* mlp_b1     = (const float*)d_in[14];
    const float* mlp_w2     = (const float*)d_in[15];
    const float* mlp_b2     = (const float*)d_in[16];
    float* out = (float*)d_out;

    float *ln1p, *zxp, *yp, *x1p, *ln2p, *mlpp;
    cudaGetSymbolAddress((void**)&ln1p, g_ln1);
    cudaGetSymbolAddress((void**)&zxp,  g_zx);
    cudaGetSymbolAddress((void**)&yp,   g_y);
    cudaGetSymbolAddress((void**)&x1p,  g_x1);
    cudaGetSymbolAddress((void**)&ln2p, g_ln2);
    cudaGetSymbolAddress((void**)&mlpp, g_mlp);

    // 1. LN1
    ln_kernel<<<ROWS, 256>>>(x, ln1_w, ln1_b, ln1p);
    // 2. zxbcdt = ln1 @ in_proj_w^T   [4096 x 4256]
    {
        dim3 g((DINPROJ + 127)/128, ROWS/128);
        gemm_nt<0><<<g, 256>>>(ln1p, in_proj_w, zxp, ROWS, DINPROJ, DM, nullptr, nullptr);
    }
    // 3. conv + silu + dt softplus
    conv_kernel<<<ROWS, 256>>>(conv_w, conv_b, dt_bias);
    // 4. selective scan (+ D skip)
    scan_kernel<<<BATCH*NH, 256>>>(A_log, Dvec);
    // 5. gate + rmsnorm
    gate_rms_kernel<<<ROWS, 256>>>(norm_w);
    // 6. x1 = x + y @ out_proj_w^T
    {
        dim3 g((DM + 127)/128, ROWS/128);
        gemm_nt<1><<<g, 256>>>(yp, out_proj_w, x1p, ROWS, DM, DI, x, nullptr);
    }
    // 7. LN2
    ln_kernel<<<ROWS, 256>>>(x1p, ln2_w, ln2_b, ln2p);
    // 8. mlp1 = gelu(ln2 @ mlp_w1^T + b1)
    {
        dim3 g((4*DM + 127)/128, ROWS/128);
        gemm_nt<2><<<g, 256>>>(ln2p, mlp_w1, mlpp, ROWS, 4*DM, DM, nullptr, mlp_b1);
    }
    // 9. out = x1 + mlp1 @ mlp_w2^T + b2
    {
        dim3 g((DM + 127)/128, ROWS/128);
        gemm_nt<3><<<g, 256>>>(mlpp, mlp_w2, out, ROWS, DM, 4*DM, x1p, mlp_b2);
    }
}

// round 4
// speedup vs baseline: 1.8590x; 1.8590x over previous
#include <cuda_runtime.h>
#include <cuda_bf16.h>
#include <math.h>
#include <stdint.h>

#define BATCH   2
#define LSEQ    2048
#define DM      1024
#define DI      2048
#define DSTATE  64
#define HD      64
#define NH      32
#define CONVDIM 2176
#define DINPROJ 4256
#define ROWS    (BATCH*LSEQ)
#define EPSF    1e-5f

// ---------------- fp32 scratch ----------------
__device__ float g_ln1[(size_t)ROWS*DM];
__device__ float g_zx [(size_t)ROWS*DINPROJ];
__device__ float g_xbc[(size_t)ROWS*CONVDIM];
__device__ float g_dt [(size_t)ROWS*NH];
__device__ float g_y  [(size_t)ROWS*DI];
__device__ float g_x1 [(size_t)ROWS*DM];
__device__ float g_ln2[(size_t)ROWS*DM];
__device__ float g_mlp[(size_t)ROWS*4*DM];

// ---------------- bf16 split scratch (hi/lo) ----------------
__device__ __nv_bfloat16 w_ip_hi[(size_t)DINPROJ*DM],  w_ip_lo[(size_t)DINPROJ*DM];
__device__ __nv_bfloat16 w_op_hi[(size_t)DM*DI],       w_op_lo[(size_t)DM*DI];
__device__ __nv_bfloat16 w_m1_hi[(size_t)4*DM*DM],     w_m1_lo[(size_t)4*DM*DM];
__device__ __nv_bfloat16 w_m2_hi[(size_t)DM*4*DM],     w_m2_lo[(size_t)DM*4*DM];
__device__ __nv_bfloat16 a_ln1_hi[(size_t)ROWS*DM],    a_ln1_lo[(size_t)ROWS*DM];
__device__ __nv_bfloat16 a_y_hi [(size_t)ROWS*DI],     a_y_lo [(size_t)ROWS*DI];
__device__ __nv_bfloat16 a_ln2_hi[(size_t)ROWS*DM],    a_ln2_lo[(size_t)ROWS*DM];
__device__ __nv_bfloat16 a_mlp_hi[(size_t)ROWS*4*DM],  a_mlp_lo[(size_t)ROWS*4*DM];

// ---------------- helpers ----------------
__device__ __forceinline__ uint32_t smem_u32(const void* p) {
    uint32_t a;
    asm("{ .reg .u64 t; cvta.to.shared.u64 t, %1; cvt.u32.u64 %0, t; }" : "=r"(a) : "l"(p));
    return a;
}
__device__ __forceinline__ void cp_async16(uint32_t saddr, const void* gaddr, uint32_t sz) {
    asm volatile("cp.async.cg.shared.global [%0], [%1], 16, %2;"
                 :: "r"(saddr), "l"(gaddr), "r"(sz));
}
__device__ __forceinline__ void cp_commit() { asm volatile("cp.async.commit_group;"); }
template<int N> __device__ __forceinline__ void cp_wait() {
    asm volatile("cp.async.wait_group %0;" :: "n"(N));
}
__device__ __forceinline__ void ldm_x4(uint32_t addr, uint32_t& r0, uint32_t& r1,
                                       uint32_t& r2, uint32_t& r3) {
    asm volatile("ldmatrix.sync.aligned.m8n8.x4.shared.b16 {%0,%1,%2,%3}, [%4];"
                 : "=r"(r0), "=r"(r1), "=r"(r2), "=r"(r3) : "r"(addr));
}
__device__ __forceinline__ void mma_bf16(float* c, const uint32_t* a, const uint32_t* b) {
    asm volatile(
        "mma.sync.aligned.m16n8k16.row.col.f32.bf16.bf16.f32 "
        "{%0,%1,%2,%3}, {%4,%5,%6,%7}, {%8,%9}, {%0,%1,%2,%3};"
        : "+f"(c[0]), "+f"(c[1]), "+f"(c[2]), "+f"(c[3])
        : "r"(a[0]), "r"(a[1]), "r"(a[2]), "r"(a[3]), "r"(b[0]), "r"(b[1]));
}

// ---------------- split conversion ----------------
__global__ void cvt_kernel(const float* __restrict__ in, __nv_bfloat16* __restrict__ hi,
                           __nv_bfloat16* __restrict__ lo, size_t n)
{
    size_t i = (size_t)blockIdx.x * blockDim.x + threadIdx.x;
    size_t stride = (size_t)gridDim.x * blockDim.x;
    for (; i < n; i += stride) {
        float v = in[i];
        __nv_bfloat16 h = __float2bfloat16(v);
        hi[i] = h;
        lo[i] = __float2bfloat16(v - __bfloat162float(h));
    }
}

// ---------------- layernorm ----------------
__global__ void ln_kernel(const float* __restrict__ in, const float* __restrict__ w,
                          const float* __restrict__ b, float* __restrict__ out)
{
    int row = blockIdx.x;
    const float* x = in + (size_t)row*DM;
    float s = 0.f, ss = 0.f;
    for (int c = threadIdx.x; c < DM; c += 256) {
        float v = x[c];
        s += v; ss += v*v;
    }
    __shared__ float red0[8], red1[8];
    #pragma unroll
    for (int o = 16; o; o >>= 1) {
        s  += __shfl_xor_sync(0xffffffffu, s, o);
        ss += __shfl_xor_sync(0xffffffffu, ss, o);
    }
    int warp = threadIdx.x >> 5, lane = threadIdx.x & 31;
    if (lane == 0) { red0[warp] = s; red1[warp] = ss; }
    __syncthreads();
    s = 0.f; ss = 0.f;
    #pragma unroll
    for (int i = 0; i < 8; i++) { s += red0[i]; ss += red1[i]; }
    float mu  = s * (1.f/DM);
    float var = ss * (1.f/DM) - mu*mu;
    float sc  = rsqrtf(var + EPSF);
    float* o = out + (size_t)row*DM;
    for (int c = threadIdx.x; c < DM; c += 256)
        o[c] = (x[c] - mu) * sc * w[c] + b[c];
}

// ---------------- HMMA split-bf16 GEMM: C[M,N] = A[M,K] @ B[N,K]^T ----------------
// Block tile 128x128, BK=32, 8 warps as 2(m) x 4(n), warp tile 64x32.
// smem pitch: 40 bf16 (80B) per 32-col row -> conflict-free cp.async stores + ldmatrix.
// EPI: 0=none, 1=+add, 2=+bias+gelu, 3=+bias+add
#define PITCHB   80          // bytes per row (32 bf16 data + 8 pad)
#define MATB     (128*PITCHB)  // 10240 bytes per matrix
#define STAGEB   (4*MATB)      // Ah, Al, Bh, Bl
#define GSMEM_BYTES (2*STAGEB) // 81920

template<int EPI>
__global__ void __launch_bounds__(256, 1)
gemm_tc(const __nv_bfloat16* __restrict__ Ahi, const __nv_bfloat16* __restrict__ Alo,
        const __nv_bfloat16* __restrict__ Bhi, const __nv_bfloat16* __restrict__ Blo,
        float* __restrict__ C, int M, int N, int K,
        const float* __restrict__ add, const float* __restrict__ bias)
{
    extern __shared__ __align__(128) char smem[];
    uint32_t sb = smem_u32(smem);
    int tid = threadIdx.x, wid = tid >> 5, lane = tid & 31;
    int bm = blockIdx.y * 128, bn = blockIdx.x * 128;
    int warp_m = wid >> 2, warp_n = wid & 3;
    int nrow_b = N - bn;

    // per-thread load mapping: 512 16B-chunks per matrix; thread does 2 per matrix
    int lr0 = tid >> 2, lc0 = (tid & 3);          // chunk tid
    int lr1 = (tid + 256) >> 2, lc1 = (tid & 3);  // chunk tid+256

    const int NK = K >> 5;  // BK=32

    auto issue_load = [&](int stage, int kc) {
        uint32_t s0 = sb + stage * STAGEB;
        int k0 = kc << 5;
        // A hi/lo (rows always valid, M multiple of 128)
        {
            size_t ga0 = (size_t)(bm + lr0) * K + k0 + lc0 * 8;
            size_t ga1 = (size_t)(bm + lr1) * K + k0 + lc1 * 8;
            cp_async16(s0 + 0*MATB + lr0*PITCHB + lc0*16, Ahi + ga0, 16);
            cp_async16(s0 + 0*MATB + lr1*PITCHB + lc1*16, Ahi + ga1, 16);
            cp_async16(s0 + 1*MATB + lr0*PITCHB + lc0*16, Alo + ga0, 16);
            cp_async16(s0 + 1*MATB + lr1*PITCHB + lc1*16, Alo + ga1, 16);
        }
        // B hi/lo (guard rows >= nrow_b: zero-fill)
        {
            int r0 = lr0 < nrow_b ? lr0 : 0;  uint32_t z0 = lr0 < nrow_b ? 16u : 0u;
            int r1 = lr1 < nrow_b ? lr1 : 0;  uint32_t z1 = lr1 < nrow_b ? 16u : 0u;
            size_t gb0 = (size_t)(bn + r0) * K + k0 + lc0 * 8;
            size_t gb1 = (size_t)(bn + r1) * K + k0 + lc1 * 8;
            cp_async16(s0 + 2*MATB + lr0*PITCHB + lc0*16, Bhi + gb0, z0);
            cp_async16(s0 + 2*MATB + lr1*PITCHB + lc1*16, Bhi + gb1, z1);
            cp_async16(s0 + 3*MATB + lr0*PITCHB + lc0*16, Blo + gb0, z0);
            cp_async16(s0 + 3*MATB + lr1*PITCHB + lc1*16, Blo + gb1, z1);
        }
        cp_commit();
    };

    float acc[4][4][4];
    #pragma unroll
    for (int i = 0; i < 4; i++)
        #pragma unroll
        for (int j = 0; j < 4; j++)
            #pragma unroll
            for (int q = 0; q < 4; q++) acc[i][j][q] = 0.f;

    issue_load(0, 0);
    if (NK > 1) issue_load(1, 1);

    // ldmatrix address components
    int a_row = warp_m * 64 + (lane & 15);     // + mt*16
    int a_colb = ((lane >> 4) << 3) * 2;       // +ks*32 bytes
    int b_row = warp_n * 32 + ((lane >> 4) << 3) + (lane & 7);  // + nh*16
    int b_colb = (((lane >> 3) & 1) << 3) * 2;                  // +ks*32 bytes

    for (int kc = 0; kc < NK; kc++) {
        int stage = kc & 1;
        uint32_t s0 = sb + stage * STAGEB;
        if (kc + 1 < NK) cp_wait<1>(); else cp_wait<0>();
        __syncthreads();

        uint32_t ah[4][4], al[4][4], bh[4][2], bl[4][2];
        #pragma unroll
        for (int ks = 0; ks < 2; ks++) {
            // load fragments
            #pragma unroll
            for (int mt = 0; mt < 4; mt++) {
                uint32_t ad = s0 + 0*MATB + (a_row + mt*16)*PITCHB + a_colb + ks*32;
                ldm_x4(ad, ah[mt][0], ah[mt][1], ah[mt][2], ah[mt][3]);
                uint32_t ad2 = ad + MATB;
                ldm_x4(ad2, al[mt][0], al[mt][1], al[mt][2], al[mt][3]);
            }
            #pragma unroll
            for (int nh = 0; nh < 2; nh++) {
                uint32_t bd = s0 + 2*MATB + (b_row + nh*16)*PITCHB + b_colb + ks*32;
                ldm_x4(bd, bh[nh*2][0], bh[nh*2][1], bh[nh*2+1][0], bh[nh*2+1][1]);
                uint32_t bd2 = bd + MATB;
                ldm_x4(bd2, bl[nh*2][0], bl[nh*2][1], bl[nh*2+1][0], bl[nh*2+1][1]);
            }
            // mma: hi*hi + hi*lo + lo*hi
            #pragma unroll
            for (int mt = 0; mt < 4; mt++)
                #pragma unroll
                for (int nt = 0; nt < 4; nt++) {
                    mma_bf16(acc[mt][nt], ah[mt], bh[nt]);
                    mma_bf16(acc[mt][nt], ah[mt], bl[nt]);
                    mma_bf16(acc[mt][nt], al[mt], bh[nt]);
                }
        }
        __syncthreads();
        if (kc + 2 < NK) issue_load(stage, kc + 2);
    }

    // epilogue
    int g = lane >> 2, tig = lane & 3;
    #pragma unroll
    for (int mt = 0; mt < 4; mt++) {
        int row0 = bm + warp_m*64 + mt*16 + g;
        #pragma unroll
        for (int nt = 0; nt < 4; nt++) {
            int col = bn + warp_n*32 + nt*8 + tig*2;
            if (col < N) {
                #pragma unroll
                for (int h = 0; h < 2; h++) {
                    int row = row0 + h*8;
                    float v0 = acc[mt][nt][h*2+0];
                    float v1 = acc[mt][nt][h*2+1];
                    size_t idx = (size_t)row * N + col;
                    if (EPI == 1) { v0 += add[idx]; v1 += add[idx+1]; }
                    if (EPI == 2) {
                        v0 += bias[col];   v0 = 0.5f*v0*(1.f + erff(v0*0.70710678118f));
                        v1 += bias[col+1]; v1 = 0.5f*v1*(1.f + erff(v1*0.70710678118f));
                    }
                    if (EPI == 3) { v0 += bias[col] + add[idx]; v1 += bias[col+1] + add[idx+1]; }
                    *(float2*)(C + idx) = make_float2(v0, v1);
                }
            }
        }
    }
}

// ---------------- conv1d(width4, causal) + SiLU + dt softplus ----------------
__global__ void conv_kernel(const float* __restrict__ conv_w, const float* __restrict__ conv_b,
                            const float* __restrict__ dt_bias)
{
    int r = blockIdx.x;
    int b = r >> 11, l = r & (LSEQ-1);
    for (int c = threadIdx.x; c < CONVDIM; c += 256) {
        float acc = conv_b[c];
        #pragma unroll
        for (int k = 0; k < 4; k++) {
            int ll = l + k - 3;
            if (ll >= 0)
                acc = fmaf(g_zx[(size_t)(b*LSEQ + ll)*DINPROJ + DI + c], conv_w[c*4 + k], acc);
        }
        acc = acc / (1.f + expf(-acc));   // SiLU
        g_xbc[(size_t)r*CONVDIM + c] = acc;
    }
    if (threadIdx.x < NH) {
        int hh = threadIdx.x;
        float raw = g_zx[(size_t)r*DINPROJ + DI + CONVDIM + hh] + dt_bias[hh];
        g_dt[r*NH + hh] = (raw > 20.f) ? raw : log1pf(expf(raw));
    }
}

// ---------------- selective scan: one block per (batch, head) ----------------
__global__ void __launch_bounds__(256) scan_kernel(const float* __restrict__ A_log,
                                                   const float* __restrict__ Dvec)
{
    int bh = blockIdx.x;
    int b = bh >> 5, h = bh & 31;
    int t = threadIdx.x;
    int p = t >> 2, nq = t & 3;

    float A_h = -expf(A_log[h]);
    float Dh  = Dvec[h];

    __shared__ float sX[2][64], sB[2][64], sC[2][64];
    __shared__ float sdt[2];

    const size_t base0 = (size_t)(b*LSEQ)*CONVDIM;
    auto load = [&](int buf, int l) {
        size_t rb = base0 + (size_t)l*CONVDIM;
        if (t < 64)        sX[buf][t]       = g_xbc[rb + h*HD + t];
        else if (t < 128)  sB[buf][t-64]    = g_xbc[rb + DI + (t-64)];
        else if (t < 192)  sC[buf][t-128]   = g_xbc[rb + DI + DSTATE + (t-128)];
        else if (t == 192) sdt[buf]         = g_dt[(b*LSEQ + l)*NH + h];
    };

    load(0, 0);
    __syncthreads();

    float st[16];
    #pragma unroll
    for (int i = 0; i < 16; i++) st[i] = 0.f;

    for (int l = 0; l < LSEQ; l++) {
        int buf = l & 1;
        if (l + 1 < LSEQ) load(buf ^ 1, l + 1);

        float dtv  = sdt[buf];
        float dA   = expf(dtv * A_h);
        float xv   = sX[buf][p];
        float coef = dtv * xv;

        const float* Bp = &sB[buf][nq*16];
        const float* Cp = &sC[buf][nq*16];
        float acc = 0.f;
        #pragma unroll
        for (int i = 0; i < 16; i++) {
            float s2 = fmaf(st[i], dA, coef * Bp[i]);
            st[i] = s2;
            acc = fmaf(s2, Cp[i], acc);
        }
        acc += __shfl_xor_sync(0xffffffffu, acc, 1);
        acc += __shfl_xor_sync(0xffffffffu, acc, 2);
        if (nq == 0)
            g_y[(size_t)(b*LSEQ + l)*DI + h*HD + p] = acc + xv * Dh;
        __syncthreads();
    }
}

// ---------------- gate (y * silu(z)) + RMSNorm ----------------
__global__ void gate_rms_kernel(const float* __restrict__ norm_w)
{
    int r = blockIdx.x;
    size_t zb = (size_t)r*DINPROJ;
    size_t yb = (size_t)r*DI;
    float ss = 0.f;
    for (int c = threadIdx.x; c < DI; c += 256) {
        float z = g_zx[zb + c];
        float v = g_y[yb + c] * (z / (1.f + expf(-z)));
        g_y[yb + c] = v;
        ss += v*v;
    }
    __shared__ float red[8];
    #pragma unroll
    for (int o = 16; o; o >>= 1) ss += __shfl_xor_sync(0xffffffffu, ss, o);
    if ((threadIdx.x & 31) == 0) red[threadIdx.x >> 5] = ss;
    __syncthreads();
    ss = 0.f;
    #pragma unroll
    for (int i = 0; i < 8; i++) ss += red[i];
    float sc = rsqrtf(ss * (1.f/DI) + EPSF);
    for (int c = threadIdx.x; c < DI; c += 256)
        g_y[yb + c] = g_y[yb + c] * sc * norm_w[c];
}

// ---------------- launch ----------------
extern "C" void kernel_launch(void* const* d_in, const int* in_sizes, int n_in,
                              void* d_out, int out_size)
{
    const float* x          = (const float*)d_in[0];
    const float* ln1_w      = (const float*)d_in[1];
    const float* ln1_b      = (const float*)d_in[2];
    const float* in_proj_w  = (const float*)d_in[3];
    const float* conv_w     = (const float*)d_in[4];
    const float* conv_b     = (const float*)d_in[5];
    const float* dt_bias    = (const float*)d_in[6];
    const float* A_log      = (const float*)d_in[7];
    const float* Dvec       = (const float*)d_in[8];
    const float* norm_w     = (const float*)d_in[9];
    const float* out_proj_w = (const float*)d_in[10];
    const float* ln2_w      = (const float*)d_in[11];
    const float* ln2_b      = (const float*)d_in[12];
    const float* mlp_w1     = (const float*)d_in[13];
    const float* mlp_b1     = (const float*)d_in[14];
    const float* mlp_w2     = (const float*)d_in[15];
    const float* mlp_b2     = (const float*)d_in[16];
    float* out = (float*)d_out;

    float *ln1p, *zxp, *yp, *x1p, *ln2p, *mlpp;
    cudaGetSymbolAddress((void**)&ln1p, g_ln1);
    cudaGetSymbolAddress((void**)&zxp,  g_zx);
    cudaGetSymbolAddress((void**)&yp,   g_y);
    cudaGetSymbolAddress((void**)&x1p,  g_x1);
    cudaGetSymbolAddress((void**)&ln2p, g_ln2);
    cudaGetSymbolAddress((void**)&mlpp, g_mlp);

    __nv_bfloat16 *wip_h, *wip_l, *wop_h, *wop_l, *wm1_h, *wm1_l, *wm2_h, *wm2_l;
    __nv_bfloat16 *aln1_h, *aln1_l, *ay_h, *ay_l, *aln2_h, *aln2_l, *amlp_h, *amlp_l;
    cudaGetSymbolAddress((void**)&wip_h, w_ip_hi);  cudaGetSymbolAddress((void**)&wip_l, w_ip_lo);
    cudaGetSymbolAddress((void**)&wop_h, w_op_hi);  cudaGetSymbolAddress((void**)&wop_l, w_op_lo);
    cudaGetSymbolAddress((void**)&wm1_h, w_m1_hi);  cudaGetSymbolAddress((void**)&wm1_l, w_m1_lo);
    cudaGetSymbolAddress((void**)&wm2_h, w_m2_hi);  cudaGetSymbolAddress((void**)&wm2_l, w_m2_lo);
    cudaGetSymbolAddress((void**)&aln1_h, a_ln1_hi); cudaGetSymbolAddress((void**)&aln1_l, a_ln1_lo);
    cudaGetSymbolAddress((void**)&ay_h,  a_y_hi);   cudaGetSymbolAddress((void**)&ay_l,  a_y_lo);
    cudaGetSymbolAddress((void**)&aln2_h, a_ln2_hi); cudaGetSymbolAddress((void**)&aln2_l, a_ln2_lo);
    cudaGetSymbolAddress((void**)&amlp_h, a_mlp_hi); cudaGetSymbolAddress((void**)&amlp_l, a_mlp_lo);

    cudaFuncSetAttribute(gemm_tc<0>, cudaFuncAttributeMaxDynamicSharedMemorySize, GSMEM_BYTES);
    cudaFuncSetAttribute(gemm_tc<1>, cudaFuncAttributeMaxDynamicSharedMemorySize, GSMEM_BYTES);
    cudaFuncSetAttribute(gemm_tc<2>, cudaFuncAttributeMaxDynamicSharedMemorySize, GSMEM_BYTES);
    cudaFuncSetAttribute(gemm_tc<3>, cudaFuncAttributeMaxDynamicSharedMemorySize, GSMEM_BYTES);

    // weight splits (independent of activations)
    cvt_kernel<<<1024, 256>>>(in_proj_w,  wip_h, wip_l, (size_t)DINPROJ*DM);
    cvt_kernel<<<1024, 256>>>(out_proj_w, wop_h, wop_l, (size_t)DM*DI);
    cvt_kernel<<<1024, 256>>>(mlp_w1,     wm1_h, wm1_l, (size_t)4*DM*DM);
    cvt_kernel<<<1024, 256>>>(mlp_w2,     wm2_h, wm2_l, (size_t)DM*4*DM);

    // 1. LN1 + split
    ln_kernel<<<ROWS, 256>>>(x, ln1_w, ln1_b, ln1p);
    cvt_kernel<<<1024, 256>>>(ln1p, aln1_h, aln1_l, (size_t)ROWS*DM);
    // 2. zxbcdt = ln1 @ in_proj_w^T
    {
        dim3 g((DINPROJ + 127)/128, ROWS/128);
        gemm_tc<0><<<g, 256, GSMEM_BYTES>>>(aln1_h, aln1_l, wip_h, wip_l, zxp,
                                            ROWS, DINPROJ, DM, nullptr, nullptr);
    }
    // 3. conv + silu + dt softplus
    conv_kernel<<<ROWS, 256>>>(conv_w, conv_b, dt_bias);
    // 4. selective scan (+ D skip)
    scan_kernel<<<BATCH*NH, 256>>>(A_log, Dvec);
    // 5. gate + rmsnorm + split
    gate_rms_kernel<<<ROWS, 256>>>(norm_w);
    cvt_kernel<<<1024, 256>>>(yp, ay_h, ay_l, (size_t)ROWS*DI);
    // 6. x1 = x + y @ out_proj_w^T
    {
        dim3 g((DM + 127)/128, ROWS/128);
        gemm_tc<1><<<g, 256, GSMEM_BYTES>>>(ay_h, ay_l, wop_h, wop_l, x1p,
                                            ROWS, DM, DI, x, nullptr);
    }
    // 7. LN2 + split
    ln_kernel<<<ROWS, 256>>>(x1p, ln2_w, ln2_b, ln2p);
    cvt_kernel<<<1024, 256>>>(ln2p, aln2_h, aln2_l, (size_t)ROWS*DM);
    // 8. mlp1 = gelu(ln2 @ mlp_w1^T + b1) + split
    {
        dim3 g((4*DM + 127)/128, ROWS/128);
        gemm_tc<2><<<g, 256, GSMEM_BYTES>>>(aln2_h, aln2_l, wm1_h, wm1_l, mlpp,
                                            ROWS, 4*DM, DM, nullptr, mlp_b1);
    }
    cvt_kernel<<<2048, 256>>>(mlpp, amlp_h, amlp_l, (size_t)ROWS*4*DM);
    // 9. out = x1 + mlp1 @ mlp_w2^T + b2
    {
        dim3 g((DM + 127)/128, ROWS/128);
        gemm_tc<3><<<g, 256, GSMEM_BYTES>>>(amlp_h, amlp_l, wm2_h, wm2_l, out,
                                            ROWS, DM, 4*DM, x1p, mlp_b2);
    }
}

// round 5
// speedup vs baseline: 1.9369x; 1.0419x over previous
#include <cuda_runtime.h>
#include <cuda_bf16.h>
#include <math.h>
#include <stdint.h>

#define BATCH   2
#define LSEQ    2048
#define DM      1024
#define DI      2048
#define DSTATE  64
#define HD      64
#define NH      32
#define CONVDIM 2176
#define DINPROJ 4256
#define ROWS    (BATCH*LSEQ)
#define EPSF    1e-5f

// ---------------- fp32 scratch ----------------
__device__ float g_zx [(size_t)ROWS*DINPROJ];
__device__ float g_xbc[(size_t)ROWS*CONVDIM];
__device__ float g_dt [(size_t)ROWS*NH];
__device__ float g_y  [(size_t)ROWS*DI];
__device__ float g_x1 [(size_t)ROWS*DM];

// ---------------- bf16 split scratch (hi/lo) ----------------
__device__ __nv_bfloat16 w_ip_hi[(size_t)DINPROJ*DM],  w_ip_lo[(size_t)DINPROJ*DM];
__device__ __nv_bfloat16 w_op_hi[(size_t)DM*DI],       w_op_lo[(size_t)DM*DI];
__device__ __nv_bfloat16 w_m1_hi[(size_t)4*DM*DM],     w_m1_lo[(size_t)4*DM*DM];
__device__ __nv_bfloat16 w_m2_hi[(size_t)DM*4*DM],     w_m2_lo[(size_t)DM*4*DM];
__device__ __nv_bfloat16 a_ln1_hi[(size_t)ROWS*DM],    a_ln1_lo[(size_t)ROWS*DM];
__device__ __nv_bfloat16 a_y_hi [(size_t)ROWS*DI],     a_y_lo [(size_t)ROWS*DI];
__device__ __nv_bfloat16 a_ln2_hi[(size_t)ROWS*DM],    a_ln2_lo[(size_t)ROWS*DM];
__device__ __nv_bfloat16 a_mlp_hi[(size_t)ROWS*4*DM],  a_mlp_lo[(size_t)ROWS*4*DM];

// ---------------- helpers ----------------
__device__ __forceinline__ uint32_t smem_u32(const void* p) {
    uint32_t a;
    asm("{ .reg .u64 t; cvta.to.shared.u64 t, %1; cvt.u32.u64 %0, t; }" : "=r"(a) : "l"(p));
    return a;
}
__device__ __forceinline__ void cp_async16(uint32_t saddr, const void* gaddr, uint32_t sz) {
    asm volatile("cp.async.cg.shared.global [%0], [%1], 16, %2;"
                 :: "r"(saddr), "l"(gaddr), "r"(sz));
}
__device__ __forceinline__ void cp_commit() { asm volatile("cp.async.commit_group;"); }
template<int N> __device__ __forceinline__ void cp_wait() {
    asm volatile("cp.async.wait_group %0;" :: "n"(N));
}
__device__ __forceinline__ void ldm_x4(uint32_t addr, uint32_t& r0, uint32_t& r1,
                                       uint32_t& r2, uint32_t& r3) {
    asm volatile("ldmatrix.sync.aligned.m8n8.x4.shared.b16 {%0,%1,%2,%3}, [%4];"
                 : "=r"(r0), "=r"(r1), "=r"(r2), "=r"(r3) : "r"(addr));
}
__device__ __forceinline__ void mma_bf16(float* c, const uint32_t* a, const uint32_t* b) {
    asm volatile(
        "mma.sync.aligned.m16n8k16.row.col.f32.bf16.bf16.f32 "
        "{%0,%1,%2,%3}, {%4,%5,%6,%7}, {%8,%9}, {%0,%1,%2,%3};"
        : "+f"(c[0]), "+f"(c[1]), "+f"(c[2]), "+f"(c[3])
        : "r"(a[0]), "r"(a[1]), "r"(a[2]), "r"(a[3]), "r"(b[0]), "r"(b[1]));
}
__device__ __forceinline__ void split1(float v, __nv_bfloat16& h, __nv_bfloat16& l) {
    h = __float2bfloat16(v);
    l = __float2bfloat16(v - __bfloat162float(h));
}

// ---------------- vectorized weight split ----------------
__global__ void cvt_kernel(const float4* __restrict__ in, uint2* __restrict__ hi,
                           uint2* __restrict__ lo, size_t n4)
{
    size_t i = (size_t)blockIdx.x * blockDim.x + threadIdx.x;
    size_t stride = (size_t)gridDim.x * blockDim.x;
    for (; i < n4; i += stride) {
        float4 v = in[i];
        __nv_bfloat16 h0,h1,h2,h3,l0,l1,l2,l3;
        split1(v.x,h0,l0); split1(v.y,h1,l1); split1(v.z,h2,l2); split1(v.w,h3,l3);
        __nv_bfloat162 hA = __halves2bfloat162(h0,h1), hB = __halves2bfloat162(h2,h3);
        __nv_bfloat162 lA = __halves2bfloat162(l0,l1), lB = __halves2bfloat162(l2,l3);
        hi[i] = make_uint2(*(uint32_t*)&hA, *(uint32_t*)&hB);
        lo[i] = make_uint2(*(uint32_t*)&lA, *(uint32_t*)&lB);
    }
}

// ---------------- layernorm + split (bf16 hi/lo out) ----------------
__global__ void ln_split_kernel(const float* __restrict__ in, const float* __restrict__ w,
                                const float* __restrict__ b,
                                __nv_bfloat16* __restrict__ hi, __nv_bfloat16* __restrict__ lo)
{
    int row = blockIdx.x;
    const float* x = in + (size_t)row*DM;
    int c0 = threadIdx.x * 4;
    float4 v = *(const float4*)(x + c0);
    float s  = v.x + v.y + v.z + v.w;
    float ss = v.x*v.x + v.y*v.y + v.z*v.z + v.w*v.w;
    __shared__ float red0[8], red1[8];
    #pragma unroll
    for (int o = 16; o; o >>= 1) {
        s  += __shfl_xor_sync(0xffffffffu, s, o);
        ss += __shfl_xor_sync(0xffffffffu, ss, o);
    }
    int warp = threadIdx.x >> 5, lane = threadIdx.x & 31;
    if (lane == 0) { red0[warp] = s; red1[warp] = ss; }
    __syncthreads();
    s = 0.f; ss = 0.f;
    #pragma unroll
    for (int i = 0; i < 8; i++) { s += red0[i]; ss += red1[i]; }
    float mu  = s * (1.f/DM);
    float var = ss * (1.f/DM) - mu*mu;
    float sc  = rsqrtf(var + EPSF);
    float4 wv = *(const float4*)(w + c0);
    float4 bv = *(const float4*)(b + c0);
    float o0 = (v.x-mu)*sc*wv.x + bv.x;
    float o1 = (v.y-mu)*sc*wv.y + bv.y;
    float o2 = (v.z-mu)*sc*wv.z + bv.z;
    float o3 = (v.w-mu)*sc*wv.w + bv.w;
    __nv_bfloat16 h0,h1,h2,h3,l0,l1,l2,l3;
    split1(o0,h0,l0); split1(o1,h1,l1); split1(o2,h2,l2); split1(o3,h3,l3);
    __nv_bfloat162 hA = __halves2bfloat162(h0,h1), hB = __halves2bfloat162(h2,h3);
    __nv_bfloat162 lA = __halves2bfloat162(l0,l1), lB = __halves2bfloat162(l2,l3);
    size_t ob = (size_t)row*DM + c0;
    *(uint2*)(hi + ob) = make_uint2(*(uint32_t*)&hA, *(uint32_t*)&hB);
    *(uint2*)(lo + ob) = make_uint2(*(uint32_t*)&lA, *(uint32_t*)&lB);
}

// ---------------- HMMA split-bf16 GEMM: C[M,N] = A[M,K] @ B[N,K]^T ----------------
// 128x128 tile, BK=32, 3-stage cp.async pipeline, ONE __syncthreads per k-chunk.
// EPI: 0=plain fp32, 1=fp32+add, 2=bias+gelu -> bf16 hi/lo split out, 3=fp32+bias+add
#define PITCHB   80
#define MATB     (128*PITCHB)
#define STAGEB   (4*MATB)        // 40960
#define NSTAGE   3
#define GSMEM_BYTES (NSTAGE*STAGEB)  // 122880

template<int EPI>
__global__ void __launch_bounds__(256, 1)
gemm_tc(const __nv_bfloat16* __restrict__ Ahi, const __nv_bfloat16* __restrict__ Alo,
        const __nv_bfloat16* __restrict__ Bhi, const __nv_bfloat16* __restrict__ Blo,
        float* __restrict__ C, int M, int N, int K,
        const float* __restrict__ add, const float* __restrict__ bias,
        __nv_bfloat16* __restrict__ Ohi, __nv_bfloat16* __restrict__ Olo)
{
    extern __shared__ __align__(128) char smem[];
    uint32_t sb = smem_u32(smem);
    int tid = threadIdx.x, wid = tid >> 5, lane = tid & 31;
    int bm = blockIdx.y * 128, bn = blockIdx.x * 128;
    int warp_m = wid >> 2, warp_n = wid & 3;
    int nrow_b = N - bn;

    int lr0 = tid >> 2, lc0 = (tid & 3);
    int lr1 = (tid + 256) >> 2, lc1 = (tid & 3);

    const int NK = K >> 5;

    auto issue_load = [&](int kc) {
        uint32_t s0 = sb + (kc % NSTAGE) * STAGEB;
        int k0 = kc << 5;
        {
            size_t ga0 = (size_t)(bm + lr0) * K + k0 + lc0 * 8;
            size_t ga1 = (size_t)(bm + lr1) * K + k0 + lc1 * 8;
            cp_async16(s0 + 0*MATB + lr0*PITCHB + lc0*16, Ahi + ga0, 16);
            cp_async16(s0 + 0*MATB + lr1*PITCHB + lc1*16, Ahi + ga1, 16);
            cp_async16(s0 + 1*MATB + lr0*PITCHB + lc0*16, Alo + ga0, 16);
            cp_async16(s0 + 1*MATB + lr1*PITCHB + lc1*16, Alo + ga1, 16);
        }
        {
            int r0 = lr0 < nrow_b ? lr0 : 0;  uint32_t z0 = lr0 < nrow_b ? 16u : 0u;
            int r1 = lr1 < nrow_b ? lr1 : 0;  uint32_t z1 = lr1 < nrow_b ? 16u : 0u;
            size_t gb0 = (size_t)(bn + r0) * K + k0 + lc0 * 8;
            size_t gb1 = (size_t)(bn + r1) * K + k0 + lc1 * 8;
            cp_async16(s0 + 2*MATB + lr0*PITCHB + lc0*16, Bhi + gb0, z0);
            cp_async16(s0 + 2*MATB + lr1*PITCHB + lc1*16, Bhi + gb1, z1);
            cp_async16(s0 + 3*MATB + lr0*PITCHB + lc0*16, Blo + gb0, z0);
            cp_async16(s0 + 3*MATB + lr1*PITCHB + lc1*16, Blo + gb1, z1);
        }
        cp_commit();
    };

    float acc[4][4][4];
    #pragma unroll
    for (int i = 0; i < 4; i++)
        #pragma unroll
        for (int j = 0; j < 4; j++)
            #pragma unroll
            for (int q = 0; q < 4; q++) acc[i][j][q] = 0.f;

    issue_load(0);
    if (NK > 1) issue_load(1);

    int a_row = warp_m * 64 + (lane & 15);
    int a_colb = ((lane >> 4) << 3) * 2;
    int b_row = warp_n * 32 + ((lane >> 4) << 3) + (lane & 7);
    int b_colb = (((lane >> 3) & 1) << 3) * 2;

    for (int kc = 0; kc < NK; kc++) {
        uint32_t s0 = sb + (kc % NSTAGE) * STAGEB;
        if (kc + 1 < NK) cp_wait<1>(); else cp_wait<0>();
        __syncthreads();
        if (kc + 2 < NK) issue_load(kc + 2);

        #pragma unroll
        for (int ks = 0; ks < 2; ks++) {
            uint32_t ah[4][4], al[4][4], bh[4][2], bl[4][2];
            #pragma unroll
            for (int mt = 0; mt < 4; mt++) {
                uint32_t ad = s0 + 0*MATB + (a_row + mt*16)*PITCHB + a_colb + ks*32;
                ldm_x4(ad, ah[mt][0], ah[mt][1], ah[mt][2], ah[mt][3]);
                ldm_x4(ad + MATB, al[mt][0], al[mt][1], al[mt][2], al[mt][3]);
            }
            #pragma unroll
            for (int nh = 0; nh < 2; nh++) {
                uint32_t bd = s0 + 2*MATB + (b_row + nh*16)*PITCHB + b_colb + ks*32;
                ldm_x4(bd, bh[nh*2][0], bh[nh*2][1], bh[nh*2+1][0], bh[nh*2+1][1]);
                ldm_x4(bd + MATB, bl[nh*2][0], bl[nh*2][1], bl[nh*2+1][0], bl[nh*2+1][1]);
            }
            #pragma unroll
            for (int mt = 0; mt < 4; mt++)
                #pragma unroll
                for (int nt = 0; nt < 4; nt++) {
                    mma_bf16(acc[mt][nt], ah[mt], bh[nt]);
                    mma_bf16(acc[mt][nt], ah[mt], bl[nt]);
                    mma_bf16(acc[mt][nt], al[mt], bh[nt]);
                }
        }
    }

    // epilogue
    int g = lane >> 2, tig = lane & 3;
    #pragma unroll
    for (int mt = 0; mt < 4; mt++) {
        int row0 = bm + warp_m*64 + mt*16 + g;
        #pragma unroll
        for (int nt = 0; nt < 4; nt++) {
            int col = bn + warp_n*32 + nt*8 + tig*2;
            if (col < N) {
                #pragma unroll
                for (int h = 0; h < 2; h++) {
                    int row = row0 + h*8;
                    float v0 = acc[mt][nt][h*2+0];
                    float v1 = acc[mt][nt][h*2+1];
                    size_t idx = (size_t)row * N + col;
                    if (EPI == 1) { v0 += add[idx]; v1 += add[idx+1]; }
                    if (EPI == 3) { v0 += bias[col] + add[idx]; v1 += bias[col+1] + add[idx+1]; }
                    if (EPI == 2) {
                        v0 += bias[col];   v0 = 0.5f*v0*(1.f + erff(v0*0.70710678118f));
                        v1 += bias[col+1]; v1 = 0.5f*v1*(1.f + erff(v1*0.70710678118f));
                        __nv_bfloat16 h0,h1,l0,l1;
                        split1(v0,h0,l0); split1(v1,h1,l1);
                        __nv_bfloat162 hp = __halves2bfloat162(h0,h1);
                        __nv_bfloat162 lp = __halves2bfloat162(l0,l1);
                        *(uint32_t*)(Ohi + idx) = *(uint32_t*)&hp;
                        *(uint32_t*)(Olo + idx) = *(uint32_t*)&lp;
                    } else {
                        *(float2*)(C + idx) = make_float2(v0, v1);
                    }
                }
            }
        }
    }
}

// ---------------- conv1d(width4, causal) + SiLU + dt softplus ----------------
__global__ void conv_kernel(const float* __restrict__ conv_w, const float* __restrict__ conv_b,
                            const float* __restrict__ dt_bias)
{
    int r = blockIdx.x;
    int b = r >> 11, l = r & (LSEQ-1);
    for (int c = threadIdx.x; c < CONVDIM; c += 256) {
        float acc = conv_b[c];
        #pragma unroll
        for (int k = 0; k < 4; k++) {
            int ll = l + k - 3;
            if (ll >= 0)
                acc = fmaf(g_zx[(size_t)(b*LSEQ + ll)*DINPROJ + DI + c], conv_w[c*4 + k], acc);
        }
        acc = acc / (1.f + expf(-acc));   // SiLU
        g_xbc[(size_t)r*CONVDIM + c] = acc;
    }
    if (threadIdx.x < NH) {
        int hh = threadIdx.x;
        float raw = g_zx[(size_t)r*DINPROJ + DI + CONVDIM + hh] + dt_bias[hh];
        g_dt[r*NH + hh] = (raw > 20.f) ? raw : log1pf(expf(raw));
    }
}

// ---------------- selective scan: one block per (batch, head) ----------------
__global__ void __launch_bounds__(256) scan_kernel(const float* __restrict__ A_log,
                                                   const float* __restrict__ Dvec)
{
    int bh = blockIdx.x;
    int b = bh >> 5, h = bh & 31;
    int t = threadIdx.x;
    int p = t >> 2, nq = t & 3;

    float A_h = -expf(A_log[h]);
    float Dh  = Dvec[h];

    __shared__ float sX[2][64], sB[2][64], sC[2][64];
    __shared__ float sdt[2];

    const size_t base0 = (size_t)(b*LSEQ)*CONVDIM;
    auto load = [&](int buf, int l) {
        size_t rb = base0 + (size_t)l*CONVDIM;
        if (t < 64)        sX[buf][t]       = g_xbc[rb + h*HD + t];
        else if (t < 128)  sB[buf][t-64]    = g_xbc[rb + DI + (t-64)];
        else if (t < 192)  sC[buf][t-128]   = g_xbc[rb + DI + DSTATE + (t-128)];
        else if (t == 192) sdt[buf]         = g_dt[(b*LSEQ + l)*NH + h];
    };

    load(0, 0);
    __syncthreads();

    float st[16];
    #pragma unroll
    for (int i = 0; i < 16; i++) st[i] = 0.f;

    for (int l = 0; l < LSEQ; l++) {
        int buf = l & 1;
        if (l + 1 < LSEQ) load(buf ^ 1, l + 1);

        float dtv  = sdt[buf];
        float dA   = expf(dtv * A_h);
        float xv   = sX[buf][p];
        float coef = dtv * xv;

        const float* Bp = &sB[buf][nq*16];
        const float* Cp = &sC[buf][nq*16];
        float acc = 0.f;
        #pragma unroll
        for (int i = 0; i < 16; i++) {
            float s2 = fmaf(st[i], dA, coef * Bp[i]);
            st[i] = s2;
            acc = fmaf(s2, Cp[i], acc);
        }
        acc += __shfl_xor_sync(0xffffffffu, acc, 1);
        acc += __shfl_xor_sync(0xffffffffu, acc, 2);
        if (nq == 0)
            g_y[(size_t)(b*LSEQ + l)*DI + h*HD + p] = acc + xv * Dh;
        __syncthreads();
    }
}

// ---------------- gate (y * silu(z)) + RMSNorm + split (bf16 hi/lo out) ----------------
__global__ void gate_rms_split_kernel(const float* __restrict__ norm_w,
                                      __nv_bfloat16* __restrict__ hi,
                                      __nv_bfloat16* __restrict__ lo)
{
    int r = blockIdx.x;
    size_t zb = (size_t)r*DINPROJ;
    size_t yb = (size_t)r*DI;
    int c0 = threadIdx.x * 8;

    float v[8];
    float ss = 0.f;
    #pragma unroll
    for (int q = 0; q < 2; q++) {
        float4 yv = *(const float4*)(g_y + yb + c0 + q*4);
        float4 zv = *(const float4*)(g_zx + zb + c0 + q*4);
        float* vv = v + q*4;
        vv[0] = yv.x * (zv.x / (1.f + expf(-zv.x)));
        vv[1] = yv.y * (zv.y / (1.f + expf(-zv.y)));
        vv[2] = yv.z * (zv.z / (1.f + expf(-zv.z)));
        vv[3] = yv.w * (zv.w / (1.f + expf(-zv.w)));
        ss += vv[0]*vv[0] + vv[1]*vv[1] + vv[2]*vv[2] + vv[3]*vv[3];
    }
    __shared__ float red[8];
    #pragma unroll
    for (int o = 16; o; o >>= 1) ss += __shfl_xor_sync(0xffffffffu, ss, o);
    if ((threadIdx.x & 31) == 0) red[threadIdx.x >> 5] = ss;
    __syncthreads();
    ss = 0.f;
    #pragma unroll
    for (int i = 0; i < 8; i++) ss += red[i];
    float sc = rsqrtf(ss * (1.f/DI) + EPSF);

    uint32_t hp[4], lp[4];
    #pragma unroll
    for (int q = 0; q < 4; q++) {
        float o0 = v[q*2+0] * sc * norm_w[c0 + q*2+0];
        float o1 = v[q*2+1] * sc * norm_w[c0 + q*2+1];
        __nv_bfloat16 h0,h1,l0,l1;
        split1(o0,h0,l0); split1(o1,h1,l1);
        __nv_bfloat162 hv = __halves2bfloat162(h0,h1);
        __nv_bfloat162 lv = __halves2bfloat162(l0,l1);
        hp[q] = *(uint32_t*)&hv; lp[q] = *(uint32_t*)&lv;
    }
    *(uint4*)(hi + yb + c0) = make_uint4(hp[0],hp[1],hp[2],hp[3]);
    *(uint4*)(lo + yb + c0) = make_uint4(lp[0],lp[1],lp[2],lp[3]);
}

// ---------------- launch ----------------
extern "C" void kernel_launch(void* const* d_in, const int* in_sizes, int n_in,
                              void* d_out, int out_size)
{
    const float* x          = (const float*)d_in[0];
    const float* ln1_w      = (const float*)d_in[1];
    const float* ln1_b      = (const float*)d_in[2];
    const float* in_proj_w  = (const float*)d_in[3];
    const float* conv_w     = (const float*)d_in[4];
    const float* conv_b     = (const float*)d_in[5];
    const float* dt_bias    = (const float*)d_in[6];
    const float* A_log      = (const float*)d_in[7];
    const float* Dvec       = (const float*)d_in[8];
    const float* norm_w     = (const float*)d_in[9];
    const float* out_proj_w = (const float*)d_in[10];
    const float* ln2_w      = (const float*)d_in[11];
    const float* ln2_b      = (const float*)d_in[12];
    const float* mlp_w1     = (const float*)d_in[13];
    const float* mlp_b1     = (const float*)d_in[14];
    const float* mlp_w2     = (const float*)d_in[15];
    const float* mlp_b2     = (const float*)d_in[16];
    float* out = (float*)d_out;

    float *zxp, *yp, *x1p;
    cudaGetSymbolAddress((void**)&zxp,  g_zx);
    cudaGetSymbolAddress((void**)&yp,   g_y);
    cudaGetSymbolAddress((void**)&x1p,  g_x1);

    __nv_bfloat16 *wip_h, *wip_l, *wop_h, *wop_l, *wm1_h, *wm1_l, *wm2_h, *wm2_l;
    __nv_bfloat16 *aln1_h, *aln1_l, *ay_h, *ay_l, *aln2_h, *aln2_l, *amlp_h, *amlp_l;
    cudaGetSymbolAddress((void**)&wip_h, w_ip_hi);  cudaGetSymbolAddress((void**)&wip_l, w_ip_lo);
    cudaGetSymbolAddress((void**)&wop_h, w_op_hi);  cudaGetSymbolAddress((void**)&wop_l, w_op_lo);
    cudaGetSymbolAddress((void**)&wm1_h, w_m1_hi);  cudaGetSymbolAddress((void**)&wm1_l, w_m1_lo);
    cudaGetSymbolAddress((void**)&wm2_h, w_m2_hi);  cudaGetSymbolAddress((void**)&wm2_l, w_m2_lo);
    cudaGetSymbolAddress((void**)&aln1_h, a_ln1_hi); cudaGetSymbolAddress((void**)&aln1_l, a_ln1_lo);
    cudaGetSymbolAddress((void**)&ay_h,  a_y_hi);   cudaGetSymbolAddress((void**)&ay_l,  a_y_lo);
    cudaGetSymbolAddress((void**)&aln2_h, a_ln2_hi); cudaGetSymbolAddress((void**)&aln2_l, a_ln2_lo);
    cudaGetSymbolAddress((void**)&amlp_h, a_mlp_hi); cudaGetSymbolAddress((void**)&amlp_l, a_mlp_lo);

    cudaFuncSetAttribute(gemm_tc<0>, cudaFuncAttributeMaxDynamicSharedMemorySize, GSMEM_BYTES);
    cudaFuncSetAttribute(gemm_tc<1>, cudaFuncAttributeMaxDynamicSharedMemorySize, GSMEM_BYTES);
    cudaFuncSetAttribute(gemm_tc<2>, cudaFuncAttributeMaxDynamicSharedMemorySize, GSMEM_BYTES);
    cudaFuncSetAttribute(gemm_tc<3>, cudaFuncAttributeMaxDynamicSharedMemorySize, GSMEM_BYTES);

    // weight splits
    cvt_kernel<<<512, 256>>>((const float4*)in_proj_w,  (uint2*)wip_h, (uint2*)wip_l, (size_t)DINPROJ*DM/4);
    cvt_kernel<<<512, 256>>>((const float4*)out_proj_w, (uint2*)wop_h, (uint2*)wop_l, (size_t)DM*DI/4);
    cvt_kernel<<<512, 256>>>((const float4*)mlp_w1,     (uint2*)wm1_h, (uint2*)wm1_l, (size_t)4*DM*DM/4);
    cvt_kernel<<<512, 256>>>((const float4*)mlp_w2,     (uint2*)wm2_h, (uint2*)wm2_l, (size_t)DM*4*DM/4);

    // 1. LN1 (fused split)
    ln_split_kernel<<<ROWS, 256>>>(x, ln1_w, ln1_b, aln1_h, aln1_l);
    // 2. zxbcdt = ln1 @ in_proj_w^T
    {
        dim3 g((DINPROJ + 127)/128, ROWS/128);
        gemm_tc<0><<<g, 256, GSMEM_BYTES>>>(aln1_h, aln1_l, wip_h, wip_l, zxp,
                                            ROWS, DINPROJ, DM, nullptr, nullptr, nullptr, nullptr);
    }
    // 3. conv + silu + dt softplus
    conv_kernel<<<ROWS, 256>>>(conv_w, conv_b, dt_bias);
    // 4. selective scan (+ D skip)
    scan_kernel<<<BATCH*NH, 256>>>(A_log, Dvec);
    // 5. gate + rmsnorm (fused split)
    gate_rms_split_kernel<<<ROWS, 256>>>(norm_w, ay_h, ay_l);
    // 6. x1 = x + y @ out_proj_w^T
    {
        dim3 g((DM + 127)/128, ROWS/128);
        gemm_tc<1><<<g, 256, GSMEM_BYTES>>>(ay_h, ay_l, wop_h, wop_l, x1p,
                                            ROWS, DM, DI, x, nullptr, nullptr, nullptr);
    }
    // 7. LN2 (fused split)
    ln_split_kernel<<<ROWS, 256>>>(x1p, ln2_w, ln2_b, aln2_h, aln2_l);
    // 8. mlp1 = gelu(ln2 @ mlp_w1^T + b1) -> bf16 hi/lo directly
    {
        dim3 g((4*DM + 127)/128, ROWS/128);
        gemm_tc<2><<<g, 256, GSMEM_BYTES>>>(aln2_h, aln2_l, wm1_h, wm1_l, nullptr,
                                            ROWS, 4*DM, DM, nullptr, mlp_b1, amlp_h, amlp_l);
    }
    // 9. out = x1 + mlp1 @ mlp_w2^T + b2
    {
        dim3 g((DM + 127)/128, ROWS/128);
        gemm_tc<3><<<g, 256, GSMEM_BYTES>>>(amlp_h, amlp_l, wm2_h, wm2_l, out,
                                            ROWS, DM, 4*DM, x1p, mlp_b2, nullptr, nullptr);
    }
}